// round 5
// baseline (speedup 1.0000x reference)
#include <cuda_runtime.h>
#include <cuda_bf16.h>
#include <math.h>
#include <stdint.h>

// ---------------------------------------------------------------------------
// Problem constants
// ---------------------------------------------------------------------------
#define NB   32
#define NL   4096
#define NH   512
#define NC   1025
#define MTOT (NB * NL)   // 131072

// GEMM tiling
#define MT   128         // m rows per CTA
#define KC   64          // k per stage
#define NSTAGES 8        // 512 / 64

// SMEM layout: per buffer, Ah/Al/Bh/Bl tiles of 128 rows x 64 bf16 (128B) + 16B pad
#define ROWB    144
#define TILEB   (128 * ROWB)          // 18432
#define BUFB    (4 * TILEB)           // 73728
#define SM_TAB  (2 * BUFB)            // 147456: w2|base|wcov|red|logit_acc
#define SMEM_TOTAL (SM_TAB + 4096)    // 151552

// ---------------------------------------------------------------------------
// Device scratch (static; no runtime allocation)
// ---------------------------------------------------------------------------
__device__ float g_base[NB * NH];
__device__ float g_logits[MTOT];
__device__ __nv_bfloat16 g_Bh[NH * 512];
__device__ __nv_bfloat16 g_Bl[NH * 512];
__device__ __nv_bfloat16 g_Ah[(size_t)MTOT * 512];   // 128 MB
__device__ __nv_bfloat16 g_Al[(size_t)MTOT * 512];   // 128 MB
__device__ float g_ctx_part[32 * NB * 512];

// ---------------------------------------------------------------------------
// helpers
// ---------------------------------------------------------------------------
__device__ __forceinline__ uint32_t smem_u32(const void* p) {
    uint32_t a;
    asm("{ .reg .u64 t; cvta.to.shared.u64 t, %1; cvt.u32.u64 %0, t; }"
        : "=r"(a) : "l"(p));
    return a;
}

__device__ __forceinline__ void ldsm4(uint32_t addr, uint32_t& r0, uint32_t& r1,
                                      uint32_t& r2, uint32_t& r3) {
    asm volatile("ldmatrix.sync.aligned.m8n8.x4.shared.b16 {%0,%1,%2,%3}, [%4];"
                 : "=r"(r0), "=r"(r1), "=r"(r2), "=r"(r3) : "r"(addr));
}

__device__ __forceinline__ void mma16816(float* d, uint32_t a0, uint32_t a1,
                                         uint32_t a2, uint32_t a3, uint32_t b0,
                                         uint32_t b1) {
    asm volatile(
        "mma.sync.aligned.m16n8k16.row.col.f32.bf16.bf16.f32 "
        "{%0,%1,%2,%3}, {%4,%5,%6,%7}, {%8,%9}, {%0,%1,%2,%3};"
        : "+f"(d[0]), "+f"(d[1]), "+f"(d[2]), "+f"(d[3])
        : "r"(a0), "r"(a1), "r"(a2), "r"(a3), "r"(b0), "r"(b1));
}

__device__ __forceinline__ void cpasync16(uint32_t dst, const void* src) {
    asm volatile("cp.async.cg.shared.global [%0], [%1], 16;"
                 :: "r"(dst), "l"(src) : "memory");
}
#define CP_COMMIT() asm volatile("cp.async.commit_group;" ::: "memory")
#define CP_WAIT0()  asm volatile("cp.async.wait_group 0;" ::: "memory")

__device__ __forceinline__ float fast_tanh(float x) {
    float t = x * 2.885390081777927f;  // 2*log2(e)
    float e;
    asm("ex2.approx.f32 %0, %1;" : "=f"(e) : "f"(t));
    float r;
    asm("rcp.approx.f32 %0, %1;" : "=f"(r) : "f"(e + 1.0f));
    return 1.0f - 2.0f * r;
}
__device__ __forceinline__ float fast_exp(float x) {
    float t = x * 1.4426950408889634f;
    float e;
    asm("ex2.approx.f32 %0, %1;" : "=f"(e) : "f"(t));
    return e;
}
__device__ __forceinline__ uint32_t pack_bf2(__nv_bfloat16 a, __nv_bfloat16 b) {
    __nv_bfloat162 v = __halves2bfloat162(a, b);
    return *reinterpret_cast<uint32_t*>(&v);
}

// ---------------------------------------------------------------------------
// K-1a: ts -> bf16 hi/lo, active tiles only
// ---------------------------------------------------------------------------
__global__ __launch_bounds__(256) void convA_kernel(const float* __restrict__ ts,
                                                    const int* __restrict__ tlen) {
    int bid = blockIdx.x;
    int b = bid >> 5;
    int l0 = (bid & 31) * 128;
    if (l0 >= tlen[b]) return;
    size_t m0 = (size_t)bid * 128;
#pragma unroll 4
    for (int i = 0; i < 64; i++) {
        int e = threadIdx.x + i * 256;  // 0..16383 float4 slots
        int r = e >> 7, q = e & 127;
        size_t idx = (m0 + r) * 512 + q * 4;
        float4 v = *(const float4*)(ts + idx);
        __nv_bfloat16 hx = __float2bfloat16(v.x);
        __nv_bfloat16 hy = __float2bfloat16(v.y);
        __nv_bfloat16 hz = __float2bfloat16(v.z);
        __nv_bfloat16 hw = __float2bfloat16(v.w);
        *(uint2*)(g_Ah + idx) = make_uint2(pack_bf2(hx, hy), pack_bf2(hz, hw));
        *(uint2*)(g_Al + idx) = make_uint2(
            pack_bf2(__float2bfloat16(v.x - __bfloat162float(hx)),
                     __float2bfloat16(v.y - __bfloat162float(hy))),
            pack_bf2(__float2bfloat16(v.z - __bfloat162float(hz)),
                     __float2bfloat16(v.w - __bfloat162float(hw))));
    }
}

// ---------------------------------------------------------------------------
// K-1b: W1[:,0:512] -> bf16 hi/lo
// ---------------------------------------------------------------------------
__global__ void convB_kernel(const float* __restrict__ W1) {
    int h = blockIdx.x;
    int k = threadIdx.x;
    float x = W1[(size_t)h * NC + k];
    __nv_bfloat16 hi = __float2bfloat16(x);
    g_Bh[h * 512 + k] = hi;
    g_Bl[h * 512 + k] = __float2bfloat16(x - __bfloat162float(hi));
}

// ---------------------------------------------------------------------------
// K0: base[b,h] = b1[h] + sum_c summary[b,c]*W1[h,512+c]
// ---------------------------------------------------------------------------
__global__ void base_kernel(const float* __restrict__ summary,
                            const float* __restrict__ W1,
                            const float* __restrict__ b1) {
    int b = blockIdx.x;
    int h = threadIdx.x;
    __shared__ float ss[512];
    ss[h] = summary[b * 512 + h];
    __syncthreads();
    const float* w = W1 + (size_t)h * NC + 512;
    float acc = b1[h];
#pragma unroll 8
    for (int c = 0; c < 512; c++) acc += ss[c] * w[c];
    g_base[b * NH + h] = acc;
}

// ---------------------------------------------------------------------------
// K1: HMMA GEMM. 512 threads = 16 warps (4m x 4n), each warp 32m x 32n.
// Per CTA: 128m x 128h tile, 4 h-tiles looped, early exit on mask.
// ---------------------------------------------------------------------------
__global__ __launch_bounds__(512, 1) void gemm_kernel(
    const float* __restrict__ W1, const float* __restrict__ W2,
    const float* __restrict__ coverage, const int* __restrict__ tlen) {
    extern __shared__ char smem[];
    const uint32_t sb = smem_u32(smem);
    const int tid = threadIdx.x;
    const int lane = tid & 31;
    const int warp = tid >> 5;
    const int wm = warp & 3;   // m quadrant (32 rows)
    const int wn = warp >> 2;  // n quadrant (32 cols)

    const int bid = blockIdx.x;
    const int b = bid >> 5;
    const int l0 = (bid & 31) * 128;
    if (l0 >= tlen[b]) return;
    const size_t m0 = (size_t)bid * MT;

    float* s_w2 = (float*)(smem + SM_TAB);           // 128
    float* s_base = (float*)(smem + SM_TAB + 512);   // 128
    float* s_wcov = (float*)(smem + SM_TAB + 1024);  // 128
    float* s_red = (float*)(smem + SM_TAB + 1536);   // 128 x 4
    float* s_lac = (float*)(smem + SM_TAB + 3584);   // 128

    if (tid < 128) s_lac[tid] = 0.0f;

    const uint32_t aBase =
        sb + (uint32_t)((wm * 32 + (lane & 15)) * ROWB + (lane >> 4) * 16);
    const uint32_t bBase =
        sb + 2 * TILEB +
        (uint32_t)((wn * 32 + (lane & 7) + ((lane >> 4) & 1) * 8) * ROWB +
                   ((lane >> 3) & 1) * 16);

    // per-thread cp.async coordinates: 1024 16B chunks per tile, 2 per thread
    const int cr0 = tid >> 3;          // row base (0..63), +64 for i=1
    const int cc = tid & 7;            // 16B chunk in row

    for (int ht = 0; ht < 4; ht++) {
        const int h0 = ht * 128;

        float acc[2][4][4];
#pragma unroll
        for (int i = 0; i < 2; i++)
#pragma unroll
            for (int j = 0; j < 4; j++)
#pragma unroll
                for (int c = 0; c < 4; c++) acc[i][j][c] = 0.0f;

        // ---- prologue: stage 0 into buffer 0 ----
        {
#pragma unroll
            for (int i = 0; i < 2; i++) {
                int r = cr0 + i * 64;
                uint32_t d = sb + (uint32_t)(r * ROWB + cc * 16);
                const size_t sa = (m0 + r) * 512 + cc * 8;
                const size_t sbofs = (size_t)(h0 + r) * 512 + cc * 8;
                cpasync16(d, g_Ah + sa);
                cpasync16(d + TILEB, g_Al + sa);
                cpasync16(d + 2 * TILEB, g_Bh + sbofs);
                cpasync16(d + 3 * TILEB, g_Bl + sbofs);
            }
            CP_COMMIT();
            if (tid < 128) {
                int h = h0 + tid;
                s_w2[tid] = W2[h];
                s_base[tid] = g_base[b * NH + h];
                s_wcov[tid] = W1[(size_t)h * NC + 1024];
            }
            CP_WAIT0();
            __syncthreads();
        }

        // ---- main loop ----
        for (int s = 0; s < NSTAGES; s++) {
            const uint32_t bo = (uint32_t)((s & 1) * BUFB);
            const uint32_t nbo = bo ^ BUFB;

            if (s < NSTAGES - 1) {
                const int k0n = (s + 1) * KC;
#pragma unroll
                for (int i = 0; i < 2; i++) {
                    int r = cr0 + i * 64;
                    uint32_t d = sb + nbo + (uint32_t)(r * ROWB + cc * 16);
                    const size_t sa = (m0 + r) * 512 + k0n + cc * 8;
                    const size_t sbofs = (size_t)(h0 + r) * 512 + k0n + cc * 8;
                    cpasync16(d, g_Ah + sa);
                    cpasync16(d + TILEB, g_Al + sa);
                    cpasync16(d + 2 * TILEB, g_Bh + sbofs);
                    cpasync16(d + 3 * TILEB, g_Bl + sbofs);
                }
                CP_COMMIT();
            }

#pragma unroll
            for (int ks = 0; ks < 4; ks++) {
                uint32_t ah0, ah1, ah2, ah3, ah4, ah5, ah6, ah7;
                uint32_t al0, al1, al2, al3, al4, al5, al6, al7;
                ldsm4(aBase + bo + ks * 32, ah0, ah1, ah2, ah3);
                ldsm4(aBase + bo + ks * 32 + 16 * ROWB, ah4, ah5, ah6, ah7);
                ldsm4(aBase + bo + TILEB + ks * 32, al0, al1, al2, al3);
                ldsm4(aBase + bo + TILEB + ks * 32 + 16 * ROWB, al4, al5, al6,
                      al7);
#pragma unroll
                for (int tp = 0; tp < 2; tp++) {
                    uint32_t bh0, bh1, bh2, bh3, bl0, bl1, bl2, bl3;
                    ldsm4(bBase + bo + ks * 32 + tp * 16 * ROWB, bh0, bh1, bh2,
                          bh3);
                    ldsm4(bBase + bo + TILEB + ks * 32 + tp * 16 * ROWB, bl0,
                          bl1, bl2, bl3);
                    // Ah x Bh
                    mma16816(acc[0][2 * tp], ah0, ah1, ah2, ah3, bh0, bh1);
                    mma16816(acc[0][2 * tp + 1], ah0, ah1, ah2, ah3, bh2, bh3);
                    mma16816(acc[1][2 * tp], ah4, ah5, ah6, ah7, bh0, bh1);
                    mma16816(acc[1][2 * tp + 1], ah4, ah5, ah6, ah7, bh2, bh3);
                    // Ah x Bl
                    mma16816(acc[0][2 * tp], ah0, ah1, ah2, ah3, bl0, bl1);
                    mma16816(acc[0][2 * tp + 1], ah0, ah1, ah2, ah3, bl2, bl3);
                    mma16816(acc[1][2 * tp], ah4, ah5, ah6, ah7, bl0, bl1);
                    mma16816(acc[1][2 * tp + 1], ah4, ah5, ah6, ah7, bl2, bl3);
                    // Al x Bh
                    mma16816(acc[0][2 * tp], al0, al1, al2, al3, bh0, bh1);
                    mma16816(acc[0][2 * tp + 1], al0, al1, al2, al3, bh2, bh3);
                    mma16816(acc[1][2 * tp], al4, al5, al6, al7, bh0, bh1);
                    mma16816(acc[1][2 * tp + 1], al4, al5, al6, al7, bh2, bh3);
                }
            }

            if (s < NSTAGES - 1) CP_WAIT0();
            __syncthreads();
        }

        // ---- epilogue for this h-tile ----
#pragma unroll
        for (int tm = 0; tm < 2; tm++) {
#pragma unroll
            for (int rh = 0; rh < 2; rh++) {
                int m_local = wm * 32 + tm * 16 + rh * 8 + (lane >> 2);
                float cov = coverage[m0 + m_local];
                float rs = 0.0f;
#pragma unroll
                for (int tn = 0; tn < 4; tn++) {
                    int h = wn * 32 + tn * 8 + (lane & 3) * 2;
                    float p0 =
                        acc[tm][tn][rh * 2 + 0] + s_base[h] + cov * s_wcov[h];
                    float p1 = acc[tm][tn][rh * 2 + 1] + s_base[h + 1] +
                               cov * s_wcov[h + 1];
                    rs += fast_tanh(p0) * s_w2[h] + fast_tanh(p1) * s_w2[h + 1];
                }
                rs += __shfl_xor_sync(0xffffffffu, rs, 1);
                rs += __shfl_xor_sync(0xffffffffu, rs, 2);
                if ((lane & 3) == 0) s_red[m_local * 4 + wn] = rs;
            }
        }
        __syncthreads();
        if (tid < 128)
            s_lac[tid] += (s_red[tid * 4] + s_red[tid * 4 + 1]) +
                          (s_red[tid * 4 + 2] + s_red[tid * 4 + 3]);
        __syncthreads();
    }

    if (tid < 128) g_logits[m0 + tid] = s_lac[tid];
}

// ---------------------------------------------------------------------------
// K3: per-batch masked softmax
// ---------------------------------------------------------------------------
__global__ __launch_bounds__(256) void softmax_kernel(const int* __restrict__ tlen,
                                                      float* __restrict__ att_out) {
    int b = blockIdx.x;
    int tid = threadIdx.x;
    __shared__ float sl[NL];
    __shared__ float rbuf[256];
    int len = tlen[b];

    for (int l = tid; l < len; l += 256) sl[l] = g_logits[b * NL + l];
    __syncthreads();

    float mx = -INFINITY;
    for (int l = tid; l < len; l += 256) mx = fmaxf(mx, sl[l]);
    rbuf[tid] = mx;
    __syncthreads();
    for (int s = 128; s > 0; s >>= 1) {
        if (tid < s) rbuf[tid] = fmaxf(rbuf[tid], rbuf[tid + s]);
        __syncthreads();
    }
    mx = rbuf[0];
    __syncthreads();

    float sum = 0.0f;
    for (int l = tid; l < len; l += 256) {
        float e = fast_exp(sl[l] - mx);
        sl[l] = e;
        sum += e;
    }
    rbuf[tid] = sum;
    __syncthreads();
    for (int s = 128; s > 0; s >>= 1) {
        if (tid < s) rbuf[tid] = rbuf[tid] + rbuf[tid + s];
        __syncthreads();
    }
    float inv = 1.0f / rbuf[0];

    for (int l = tid; l < NL; l += 256)
        att_out[b * NL + l] = (l < len) ? sl[l] * inv : 0.0f;
}

// ---------------------------------------------------------------------------
// K4/K5: context partials + reduce
// ---------------------------------------------------------------------------
__global__ __launch_bounds__(256) void ctx_part_kernel(
    const float* __restrict__ ts, const float* __restrict__ att,
    const int* __restrict__ tlen) {
    int b = blockIdx.x;
    int c = blockIdx.y;
    int tid = threadIdx.x;
    float* out = g_ctx_part + ((size_t)c * NB + b) * 512;

    if (c * 128 >= tlen[b]) {
        out[tid] = 0.0f;
        out[tid + 256] = 0.0f;
        return;
    }

    __shared__ float sa[128];
    if (tid < 128) sa[tid] = att[b * NL + c * 128 + tid];
    __syncthreads();

    const float* base = ts + ((size_t)b * NL + c * 128) * 512;
    float a0 = 0.f, a1 = 0.f;
#pragma unroll 4
    for (int l = 0; l < 128; l++) {
        float wv = sa[l];
        a0 += wv * base[(size_t)l * 512 + tid];
        a1 += wv * base[(size_t)l * 512 + 256 + tid];
    }
    out[tid] = a0;
    out[tid + 256] = a1;
}

__global__ __launch_bounds__(512) void ctx_reduce_kernel(float* __restrict__ ctx) {
    int b = blockIdx.x;
    int f = threadIdx.x;
    float s = 0.0f;
#pragma unroll
    for (int c = 0; c < 32; c++) s += g_ctx_part[((size_t)c * NB + b) * 512 + f];
    ctx[b * 512 + f] = s;
}

// ---------------------------------------------------------------------------
// Launch
// ---------------------------------------------------------------------------
extern "C" void kernel_launch(void* const* d_in, const int* in_sizes, int n_in,
                              void* d_out, int out_size) {
    const float* ts  = (const float*)d_in[0];
    const float* ss  = (const float*)d_in[1];
    const float* cov = (const float*)d_in[2];
    const float* W1  = (const float*)d_in[3];
    const float* b1  = (const float*)d_in[4];
    const float* W2  = (const float*)d_in[5];
    const int*   tl  = (const int*)d_in[7];
    float* out = (float*)d_out;
    float* ctx_out = out;             // [32,512]
    float* att_out = out + NB * 512;  // [32,4096]

    cudaFuncSetAttribute(gemm_kernel,
                         cudaFuncAttributeMaxDynamicSharedMemorySize, SMEM_TOTAL);

    convA_kernel<<<1024, 256>>>(ts, tl);
    convB_kernel<<<NH, 512>>>(W1);
    base_kernel<<<NB, 512>>>(ss, W1, b1);
    gemm_kernel<<<1024, 512, SMEM_TOTAL>>>(W1, W2, cov, tl);
    softmax_kernel<<<NB, 256>>>(tl, att_out);
    ctx_part_kernel<<<dim3(NB, 32), 256>>>(ts, att_out, tl);
    ctx_reduce_kernel<<<NB, 512>>>(ctx_out);
}

// round 6
// speedup vs baseline: 1.8117x; 1.8117x over previous
#include <cuda_runtime.h>
#include <cuda_fp16.h>
#include <math.h>
#include <stdint.h>

// ---------------------------------------------------------------------------
// Problem constants
// ---------------------------------------------------------------------------
#define NB   32
#define NL   4096
#define NH   512
#define NC   1025
#define MTOT (NB * NL)   // 131072

// GEMM tiling
#define MT   128         // m rows per CTA
#define KC   64          // k per stage
#define NSTAGES 8        // 512 / 64

// SMEM: per buffer, A/B tiles of 128 rows x 64 fp16 (128B) + 16B pad per row
#define ROWB    144
#define TILEB   (128 * ROWB)          // 18432
#define BUFB    (2 * TILEB)           // 36864
#define SM_TAB  (2 * BUFB)            // 73728: w2|base|wcov|red|logit_acc
#define SMEM_TOTAL (SM_TAB + 4096)    // 77824

// ---------------------------------------------------------------------------
// Device scratch (static; no runtime allocation)
// ---------------------------------------------------------------------------
__device__ float g_base[NB * NH];
__device__ float g_logits[MTOT];
__device__ __half g_Bf[NH * 512];                  // W1[:,0:512] fp16
__device__ __half g_Af[(size_t)MTOT * 512];        // ts fp16 (128 MB)
__device__ float g_ctx_part[32 * NB * 512];

// ---------------------------------------------------------------------------
// helpers
// ---------------------------------------------------------------------------
__device__ __forceinline__ uint32_t smem_u32(const void* p) {
    uint32_t a;
    asm("{ .reg .u64 t; cvta.to.shared.u64 t, %1; cvt.u32.u64 %0, t; }"
        : "=r"(a) : "l"(p));
    return a;
}

__device__ __forceinline__ void ldsm4(uint32_t addr, uint32_t& r0, uint32_t& r1,
                                      uint32_t& r2, uint32_t& r3) {
    asm volatile("ldmatrix.sync.aligned.m8n8.x4.shared.b16 {%0,%1,%2,%3}, [%4];"
                 : "=r"(r0), "=r"(r1), "=r"(r2), "=r"(r3) : "r"(addr));
}

__device__ __forceinline__ void mma16816(float* d, uint32_t a0, uint32_t a1,
                                         uint32_t a2, uint32_t a3, uint32_t b0,
                                         uint32_t b1) {
    asm volatile(
        "mma.sync.aligned.m16n8k16.row.col.f32.f16.f16.f32 "
        "{%0,%1,%2,%3}, {%4,%5,%6,%7}, {%8,%9}, {%0,%1,%2,%3};"
        : "+f"(d[0]), "+f"(d[1]), "+f"(d[2]), "+f"(d[3])
        : "r"(a0), "r"(a1), "r"(a2), "r"(a3), "r"(b0), "r"(b1));
}

__device__ __forceinline__ void cpasync16(uint32_t dst, const void* src) {
    asm volatile("cp.async.cg.shared.global [%0], [%1], 16;"
                 :: "r"(dst), "l"(src) : "memory");
}
#define CP_COMMIT() asm volatile("cp.async.commit_group;" ::: "memory")
#define CP_WAIT0()  asm volatile("cp.async.wait_group 0;" ::: "memory")

__device__ __forceinline__ float fast_tanh(float x) {
    float t = x * 2.885390081777927f;  // 2*log2(e)
    float e;
    asm("ex2.approx.f32 %0, %1;" : "=f"(e) : "f"(t));
    float r;
    asm("rcp.approx.f32 %0, %1;" : "=f"(r) : "f"(e + 1.0f));
    return 1.0f - 2.0f * r;
}
__device__ __forceinline__ float fast_exp(float x) {
    float t = x * 1.4426950408889634f;
    float e;
    asm("ex2.approx.f32 %0, %1;" : "=f"(e) : "f"(t));
    return e;
}
__device__ __forceinline__ uint32_t pack_h2(__half a, __half b) {
    __half2 v = __halves2half2(a, b);
    return *reinterpret_cast<uint32_t*>(&v);
}

// ---------------------------------------------------------------------------
// K-1a: ts -> fp16, active tiles only
// ---------------------------------------------------------------------------
__global__ __launch_bounds__(256) void convA_kernel(const float* __restrict__ ts,
                                                    const int* __restrict__ tlen) {
    int bid = blockIdx.x;
    int b = bid >> 5;
    int l0 = (bid & 31) * 128;
    if (l0 >= tlen[b]) return;
    size_t m0 = (size_t)bid * 128;
#pragma unroll 4
    for (int i = 0; i < 64; i++) {
        int e = threadIdx.x + i * 256;  // 0..16383 float4 slots
        int r = e >> 7, q = e & 127;
        size_t idx = (m0 + r) * 512 + q * 4;
        float4 v = *(const float4*)(ts + idx);
        *(uint2*)(g_Af + idx) =
            make_uint2(pack_h2(__float2half_rn(v.x), __float2half_rn(v.y)),
                       pack_h2(__float2half_rn(v.z), __float2half_rn(v.w)));
    }
}

// ---------------------------------------------------------------------------
// K-1b: W1[:,0:512] -> fp16
// ---------------------------------------------------------------------------
__global__ void convB_kernel(const float* __restrict__ W1) {
    int h = blockIdx.x;
    int k = threadIdx.x;
    g_Bf[h * 512 + k] = __float2half_rn(W1[(size_t)h * NC + k]);
}

// ---------------------------------------------------------------------------
// K0: base[b,h] = b1[h] + sum_c summary[b,c]*W1[h,512+c]  (exact fp32)
// ---------------------------------------------------------------------------
__global__ void base_kernel(const float* __restrict__ summary,
                            const float* __restrict__ W1,
                            const float* __restrict__ b1) {
    int b = blockIdx.x;
    int h = threadIdx.x;
    __shared__ float ss[512];
    ss[h] = summary[b * 512 + h];
    __syncthreads();
    const float* w = W1 + (size_t)h * NC + 512;
    float acc = b1[h];
#pragma unroll 8
    for (int c = 0; c < 512; c++) acc += ss[c] * w[c];
    g_base[b * NH + h] = acc;
}

// ---------------------------------------------------------------------------
// K1: HMMA GEMM (fp16 single pass). 512 threads = 16 warps (4m x 4n),
// each warp 32m x 32n. Per CTA: 128m x 128h tile, 4 h-tiles looped.
// ---------------------------------------------------------------------------
__global__ __launch_bounds__(512, 1) void gemm_kernel(
    const float* __restrict__ W1, const float* __restrict__ W2,
    const float* __restrict__ coverage, const int* __restrict__ tlen) {
    extern __shared__ char smem[];
    const uint32_t sb = smem_u32(smem);
    const int tid = threadIdx.x;
    const int lane = tid & 31;
    const int warp = tid >> 5;
    const int wm = warp & 3;   // m quadrant (32 rows)
    const int wn = warp >> 2;  // n quadrant (32 cols)

    const int bid = blockIdx.x;
    const int b = bid >> 5;
    const int l0 = (bid & 31) * 128;
    if (l0 >= tlen[b]) return;
    const size_t m0 = (size_t)bid * MT;

    float* s_w2 = (float*)(smem + SM_TAB);           // 128
    float* s_base = (float*)(smem + SM_TAB + 512);   // 128
    float* s_wcov = (float*)(smem + SM_TAB + 1024);  // 128
    float* s_red = (float*)(smem + SM_TAB + 1536);   // 128 x 4
    float* s_lac = (float*)(smem + SM_TAB + 3584);   // 128

    if (tid < 128) s_lac[tid] = 0.0f;

    const uint32_t aBase =
        sb + (uint32_t)((wm * 32 + (lane & 15)) * ROWB + (lane >> 4) * 16);
    const uint32_t bBase =
        sb + TILEB +
        (uint32_t)((wn * 32 + (lane & 7) + ((lane >> 4) & 1) * 8) * ROWB +
                   ((lane >> 3) & 1) * 16);

    // per-thread cp.async coordinates: 1024 16B chunks per tile, 2 per thread
    const int cr0 = tid >> 3;          // row base (0..63), +64 for i=1
    const int cc = tid & 7;            // 16B chunk in row

    for (int ht = 0; ht < 4; ht++) {
        const int h0 = ht * 128;

        float acc[2][4][4];
#pragma unroll
        for (int i = 0; i < 2; i++)
#pragma unroll
            for (int j = 0; j < 4; j++)
#pragma unroll
                for (int c = 0; c < 4; c++) acc[i][j][c] = 0.0f;

        // ---- prologue: stage 0 into buffer 0 ----
        {
#pragma unroll
            for (int i = 0; i < 2; i++) {
                int r = cr0 + i * 64;
                uint32_t d = sb + (uint32_t)(r * ROWB + cc * 16);
                cpasync16(d, g_Af + (m0 + r) * 512 + cc * 8);
                cpasync16(d + TILEB, g_Bf + (size_t)(h0 + r) * 512 + cc * 8);
            }
            CP_COMMIT();
            if (tid < 128) {
                int h = h0 + tid;
                s_w2[tid] = W2[h];
                s_base[tid] = g_base[b * NH + h];
                s_wcov[tid] = W1[(size_t)h * NC + 1024];
            }
            CP_WAIT0();
            __syncthreads();
        }

        // ---- main loop ----
        for (int s = 0; s < NSTAGES; s++) {
            const uint32_t bo = (uint32_t)((s & 1) * BUFB);
            const uint32_t nbo = bo ^ BUFB;

            if (s < NSTAGES - 1) {
                const int k0n = (s + 1) * KC;
#pragma unroll
                for (int i = 0; i < 2; i++) {
                    int r = cr0 + i * 64;
                    uint32_t d = sb + nbo + (uint32_t)(r * ROWB + cc * 16);
                    cpasync16(d, g_Af + (m0 + r) * 512 + k0n + cc * 8);
                    cpasync16(d + TILEB,
                              g_Bf + (size_t)(h0 + r) * 512 + k0n + cc * 8);
                }
                CP_COMMIT();
            }

#pragma unroll
            for (int ks = 0; ks < 4; ks++) {
                uint32_t a0, a1, a2, a3, a4, a5, a6, a7;
                ldsm4(aBase + bo + ks * 32, a0, a1, a2, a3);
                ldsm4(aBase + bo + ks * 32 + 16 * ROWB, a4, a5, a6, a7);
#pragma unroll
                for (int tp = 0; tp < 2; tp++) {
                    uint32_t b0, b1, b2, b3;
                    ldsm4(bBase + bo + ks * 32 + tp * 16 * ROWB, b0, b1, b2, b3);
                    mma16816(acc[0][2 * tp], a0, a1, a2, a3, b0, b1);
                    mma16816(acc[0][2 * tp + 1], a0, a1, a2, a3, b2, b3);
                    mma16816(acc[1][2 * tp], a4, a5, a6, a7, b0, b1);
                    mma16816(acc[1][2 * tp + 1], a4, a5, a6, a7, b2, b3);
                }
            }

            if (s < NSTAGES - 1) CP_WAIT0();
            __syncthreads();
        }

        // ---- epilogue for this h-tile ----
#pragma unroll
        for (int tm = 0; tm < 2; tm++) {
#pragma unroll
            for (int rh = 0; rh < 2; rh++) {
                int m_local = wm * 32 + tm * 16 + rh * 8 + (lane >> 2);
                float cov = coverage[m0 + m_local];
                float rs = 0.0f;
#pragma unroll
                for (int tn = 0; tn < 4; tn++) {
                    int h = wn * 32 + tn * 8 + (lane & 3) * 2;
                    float p0 =
                        acc[tm][tn][rh * 2 + 0] + s_base[h] + cov * s_wcov[h];
                    float p1 = acc[tm][tn][rh * 2 + 1] + s_base[h + 1] +
                               cov * s_wcov[h + 1];
                    rs += fast_tanh(p0) * s_w2[h] + fast_tanh(p1) * s_w2[h + 1];
                }
                rs += __shfl_xor_sync(0xffffffffu, rs, 1);
                rs += __shfl_xor_sync(0xffffffffu, rs, 2);
                if ((lane & 3) == 0) s_red[m_local * 4 + wn] = rs;
            }
        }
        __syncthreads();
        if (tid < 128)
            s_lac[tid] += (s_red[tid * 4] + s_red[tid * 4 + 1]) +
                          (s_red[tid * 4 + 2] + s_red[tid * 4 + 3]);
        __syncthreads();
    }

    if (tid < 128) g_logits[m0 + tid] = s_lac[tid];
}

// ---------------------------------------------------------------------------
// K3: per-batch masked softmax
// ---------------------------------------------------------------------------
__global__ __launch_bounds__(256) void softmax_kernel(const int* __restrict__ tlen,
                                                      float* __restrict__ att_out) {
    int b = blockIdx.x;
    int tid = threadIdx.x;
    __shared__ float sl[NL];
    __shared__ float rbuf[256];
    int len = tlen[b];

    for (int l = tid; l < len; l += 256) sl[l] = g_logits[b * NL + l];
    __syncthreads();

    float mx = -INFINITY;
    for (int l = tid; l < len; l += 256) mx = fmaxf(mx, sl[l]);
    rbuf[tid] = mx;
    __syncthreads();
    for (int s = 128; s > 0; s >>= 1) {
        if (tid < s) rbuf[tid] = fmaxf(rbuf[tid], rbuf[tid + s]);
        __syncthreads();
    }
    mx = rbuf[0];
    __syncthreads();

    float sum = 0.0f;
    for (int l = tid; l < len; l += 256) {
        float e = fast_exp(sl[l] - mx);
        sl[l] = e;
        sum += e;
    }
    rbuf[tid] = sum;
    __syncthreads();
    for (int s = 128; s > 0; s >>= 1) {
        if (tid < s) rbuf[tid] = rbuf[tid] + rbuf[tid + s];
        __syncthreads();
    }
    float inv = 1.0f / rbuf[0];

    for (int l = tid; l < NL; l += 256)
        att_out[b * NL + l] = (l < len) ? sl[l] * inv : 0.0f;
}

// ---------------------------------------------------------------------------
// K4/K5: context partials + reduce
// ---------------------------------------------------------------------------
__global__ __launch_bounds__(256) void ctx_part_kernel(
    const float* __restrict__ ts, const float* __restrict__ att,
    const int* __restrict__ tlen) {
    int b = blockIdx.x;
    int c = blockIdx.y;
    int tid = threadIdx.x;
    float* out = g_ctx_part + ((size_t)c * NB + b) * 512;

    if (c * 128 >= tlen[b]) {
        out[tid] = 0.0f;
        out[tid + 256] = 0.0f;
        return;
    }

    __shared__ float sa[128];
    if (tid < 128) sa[tid] = att[b * NL + c * 128 + tid];
    __syncthreads();

    const float* base = ts + ((size_t)b * NL + c * 128) * 512;
    float a0 = 0.f, a1 = 0.f;
#pragma unroll 4
    for (int l = 0; l < 128; l++) {
        float wv = sa[l];
        a0 += wv * base[(size_t)l * 512 + tid];
        a1 += wv * base[(size_t)l * 512 + 256 + tid];
    }
    out[tid] = a0;
    out[tid + 256] = a1;
}

__global__ __launch_bounds__(512) void ctx_reduce_kernel(float* __restrict__ ctx) {
    int b = blockIdx.x;
    int f = threadIdx.x;
    float s = 0.0f;
#pragma unroll
    for (int c = 0; c < 32; c++) s += g_ctx_part[((size_t)c * NB + b) * 512 + f];
    ctx[b * 512 + f] = s;
}

// ---------------------------------------------------------------------------
// Launch
// ---------------------------------------------------------------------------
extern "C" void kernel_launch(void* const* d_in, const int* in_sizes, int n_in,
                              void* d_out, int out_size) {
    const float* ts  = (const float*)d_in[0];
    const float* ss  = (const float*)d_in[1];
    const float* cov = (const float*)d_in[2];
    const float* W1  = (const float*)d_in[3];
    const float* b1  = (const float*)d_in[4];
    const float* W2  = (const float*)d_in[5];
    const int*   tl  = (const int*)d_in[7];
    float* out = (float*)d_out;
    float* ctx_out = out;             // [32,512]
    float* att_out = out + NB * 512;  // [32,4096]

    cudaFuncSetAttribute(gemm_kernel,
                         cudaFuncAttributeMaxDynamicSharedMemorySize, SMEM_TOTAL);

    convA_kernel<<<1024, 256>>>(ts, tl);
    convB_kernel<<<NH, 512>>>(W1);
    base_kernel<<<NB, 512>>>(ss, W1, b1);
    gemm_kernel<<<1024, 512, SMEM_TOTAL>>>(W1, W2, cov, tl);
    softmax_kernel<<<NB, 256>>>(tl, att_out);
    ctx_part_kernel<<<dim3(NB, 32), 256>>>(ts, att_out, tl);
    ctx_reduce_kernel<<<NB, 512>>>(ctx_out);
}

// round 7
// speedup vs baseline: 1.8682x; 1.0312x over previous
#include <cuda_runtime.h>
#include <cuda_fp16.h>
#include <math.h>
#include <stdint.h>

// ---------------------------------------------------------------------------
// Problem constants
// ---------------------------------------------------------------------------
#define NB   32
#define NL   4096
#define NH   512
#define NC   1025
#define MTOT (NB * NL)   // 131072

#define MT   128         // m rows per CTA
#define KC   128         // k per B stage
#define NST  16          // 4 h-tiles x 4 k-stages

// SMEM layout
#define A_ROWB 1040                    // 512 fp16 + 16B pad
#define SM_A   0
#define A_BYTES (128 * A_ROWB)         // 133120
#define B_ROWB 272                     // 128 fp16 + 16B pad
#define B_TILE (128 * B_ROWB)          // 34816
#define SM_B   A_BYTES
#define SM_TAB (A_BYTES + 2 * B_TILE)  // 202752
// tables: w2[512] base[512] wcov[512] red[512] lac[128]
#define SMEM_TOTAL (SM_TAB + 8704)     // 211456

// ---------------------------------------------------------------------------
// Device scratch (static; no runtime allocation)
// ---------------------------------------------------------------------------
__device__ float g_base[NB * NH];
__device__ float g_logits[MTOT];
__device__ __half g_Bf[NH * 512];             // W1[:,0:512] fp16
__device__ __half g_Af[(size_t)MTOT * 512];   // ts fp16 (128 MB)
__device__ float g_ctx_part[32 * NB * 512];

// ---------------------------------------------------------------------------
// helpers
// ---------------------------------------------------------------------------
__device__ __forceinline__ uint32_t smem_u32(const void* p) {
    uint32_t a;
    asm("{ .reg .u64 t; cvta.to.shared.u64 t, %1; cvt.u32.u64 %0, t; }"
        : "=r"(a) : "l"(p));
    return a;
}

__device__ __forceinline__ void ldsm4(uint32_t addr, uint32_t& r0, uint32_t& r1,
                                      uint32_t& r2, uint32_t& r3) {
    asm volatile("ldmatrix.sync.aligned.m8n8.x4.shared.b16 {%0,%1,%2,%3}, [%4];"
                 : "=r"(r0), "=r"(r1), "=r"(r2), "=r"(r3) : "r"(addr));
}

__device__ __forceinline__ void mma16816(float* d, uint32_t a0, uint32_t a1,
                                         uint32_t a2, uint32_t a3, uint32_t b0,
                                         uint32_t b1) {
    asm volatile(
        "mma.sync.aligned.m16n8k16.row.col.f32.f16.f16.f32 "
        "{%0,%1,%2,%3}, {%4,%5,%6,%7}, {%8,%9}, {%0,%1,%2,%3};"
        : "+f"(d[0]), "+f"(d[1]), "+f"(d[2]), "+f"(d[3])
        : "r"(a0), "r"(a1), "r"(a2), "r"(a3), "r"(b0), "r"(b1));
}

__device__ __forceinline__ void cpasync16(uint32_t dst, const void* src) {
    asm volatile("cp.async.cg.shared.global [%0], [%1], 16;"
                 :: "r"(dst), "l"(src) : "memory");
}
#define CP_COMMIT() asm volatile("cp.async.commit_group;" ::: "memory")
#define CP_WAIT0()  asm volatile("cp.async.wait_group 0;" ::: "memory")

__device__ __forceinline__ float fast_tanh(float x) {
    float t = x * 2.885390081777927f;  // 2*log2(e)
    float e;
    asm("ex2.approx.f32 %0, %1;" : "=f"(e) : "f"(t));
    float r;
    asm("rcp.approx.f32 %0, %1;" : "=f"(r) : "f"(e + 1.0f));
    return 1.0f - 2.0f * r;
}
__device__ __forceinline__ float fast_exp(float x) {
    float t = x * 1.4426950408889634f;
    float e;
    asm("ex2.approx.f32 %0, %1;" : "=f"(e) : "f"(t));
    return e;
}
__device__ __forceinline__ uint32_t pack_h2(__half a, __half b) {
    __half2 v = __halves2half2(a, b);
    return *reinterpret_cast<uint32_t*>(&v);
}

// ---------------------------------------------------------------------------
// K-1a: ts -> fp16, active tiles only
// ---------------------------------------------------------------------------
__global__ __launch_bounds__(256) void convA_kernel(const float* __restrict__ ts,
                                                    const int* __restrict__ tlen) {
    int bid = blockIdx.x;
    int b = bid >> 5;
    int l0 = (bid & 31) * 128;
    if (l0 >= tlen[b]) return;
    size_t m0 = (size_t)bid * 128;
#pragma unroll 4
    for (int i = 0; i < 64; i++) {
        int e = threadIdx.x + i * 256;
        int r = e >> 7, q = e & 127;
        size_t idx = (m0 + r) * 512 + q * 4;
        float4 v = *(const float4*)(ts + idx);
        *(uint2*)(g_Af + idx) =
            make_uint2(pack_h2(__float2half_rn(v.x), __float2half_rn(v.y)),
                       pack_h2(__float2half_rn(v.z), __float2half_rn(v.w)));
    }
}

// ---------------------------------------------------------------------------
// K-1b: W1[:,0:512] -> fp16
// ---------------------------------------------------------------------------
__global__ void convB_kernel(const float* __restrict__ W1) {
    int h = blockIdx.x;
    int k = threadIdx.x;
    g_Bf[h * 512 + k] = __float2half_rn(W1[(size_t)h * NC + k]);
}

// ---------------------------------------------------------------------------
// K0: base[b,h] = b1[h] + sum_c summary[b,c]*W1[h,512+c]  (exact fp32)
// ---------------------------------------------------------------------------
__global__ void base_kernel(const float* __restrict__ summary,
                            const float* __restrict__ W1,
                            const float* __restrict__ b1) {
    int b = blockIdx.x;
    int h = threadIdx.x;
    __shared__ float ss[512];
    ss[h] = summary[b * 512 + h];
    __syncthreads();
    const float* w = W1 + (size_t)h * NC + 512;
    float acc = b1[h];
#pragma unroll 8
    for (int c = 0; c < 512; c++) acc += ss[c] * w[c];
    g_base[b * NH + h] = acc;
}

// ---------------------------------------------------------------------------
// K1: HMMA GEMM. A tile resident in SMEM; flat 16-stage B pipeline.
// 512 threads = 16 warps (4m x 4n), each warp 32m x 32n.
// ---------------------------------------------------------------------------
__global__ __launch_bounds__(512, 1) void gemm_kernel(
    const float* __restrict__ W1, const float* __restrict__ W2,
    const float* __restrict__ coverage, const int* __restrict__ tlen) {
    extern __shared__ char smem[];
    const uint32_t sb = smem_u32(smem);
    const int tid = threadIdx.x;
    const int lane = tid & 31;
    const int warp = tid >> 5;
    const int wm = warp & 3;   // m quadrant (32 rows)
    const int wn = warp >> 2;  // n quadrant (32 cols)

    const int bid = blockIdx.x;
    const int b = bid >> 5;
    const int l0 = (bid & 31) * 128;
    if (l0 >= tlen[b]) return;
    const size_t m0 = (size_t)bid * MT;

    float* s_w2 = (float*)(smem + SM_TAB);            // 512
    float* s_base = (float*)(smem + SM_TAB + 2048);   // 512
    float* s_wcov = (float*)(smem + SM_TAB + 4096);   // 512
    float* s_red = (float*)(smem + SM_TAB + 6144);    // 128 x 4
    float* s_lac = (float*)(smem + SM_TAB + 8192);    // 128

    if (tid < 128) s_lac[tid] = 0.0f;

    // ---- prologue: A full tile + tables + B stage 0 ----
    {
        // A: 8192 16B chunks
#pragma unroll
        for (int i = 0; i < 16; i++) {
            int e = tid + i * 512;
            int r = e >> 6, c = e & 63;
            cpasync16(sb + (uint32_t)(r * A_ROWB + c * 16),
                      g_Af + (m0 + r) * 512 + c * 8);
        }
        // B stage 0 (ht=0, k0=0): 2048 chunks
#pragma unroll
        for (int i = 0; i < 4; i++) {
            int e = tid + i * 512;
            int r = e >> 4, c = e & 15;
            cpasync16(sb + SM_B + (uint32_t)(r * B_ROWB + c * 16),
                      g_Bf + (size_t)r * 512 + c * 8);
        }
        CP_COMMIT();
        // tables (512 entries each)
        s_w2[tid] = W2[tid];
        s_base[tid] = g_base[b * NH + tid];
        s_wcov[tid] = W1[(size_t)tid * NC + 1024];
        CP_WAIT0();
        __syncthreads();
    }

    const uint32_t aBase =
        sb + (uint32_t)((wm * 32 + (lane & 15)) * A_ROWB + (lane >> 4) * 16);
    const uint32_t bBase0 =
        sb + SM_B +
        (uint32_t)((wn * 32 + (lane & 7) + ((lane >> 4) & 1) * 8) * B_ROWB +
                   ((lane >> 3) & 1) * 16);

    float acc[2][4][4];
#pragma unroll
    for (int i = 0; i < 2; i++)
#pragma unroll
        for (int j = 0; j < 4; j++)
#pragma unroll
            for (int c = 0; c < 4; c++) acc[i][j][c] = 0.0f;

    const int cr = tid >> 4;   // B cp.async row base (0..31), +32 per i
    const int ccB = tid & 15;  // 16B chunk in B row

    for (int g = 0; g < NST; g++) {
        const uint32_t bo = (uint32_t)((g & 1) * B_TILE);

        // issue next B stage into the other buffer
        if (g < NST - 1) {
            const int gn = g + 1;
            const int htn = gn >> 2, sn = gn & 3;
            const uint32_t nbo = (uint32_t)((gn & 1) * B_TILE);
#pragma unroll
            for (int i = 0; i < 4; i++) {
                int r = cr + i * 32;
                cpasync16(sb + SM_B + nbo + (uint32_t)(r * B_ROWB + ccB * 16),
                          g_Bf + (size_t)(htn * 128 + r) * 512 + sn * 128 +
                              ccB * 8);
            }
            CP_COMMIT();
        }

        // compute stage g: A columns [s*128, s*128+128), B buffer bo
        const uint32_t aOff = (uint32_t)((g & 3) * 256);
#pragma unroll
        for (int ks = 0; ks < 8; ks++) {
            uint32_t a0, a1, a2, a3, a4, a5, a6, a7;
            ldsm4(aBase + aOff + ks * 32, a0, a1, a2, a3);
            ldsm4(aBase + aOff + ks * 32 + 16 * A_ROWB, a4, a5, a6, a7);
#pragma unroll
            for (int tp = 0; tp < 2; tp++) {
                uint32_t b0, b1, b2, b3;
                ldsm4(bBase0 + bo + ks * 32 + tp * 16 * B_ROWB, b0, b1, b2, b3);
                mma16816(acc[0][2 * tp], a0, a1, a2, a3, b0, b1);
                mma16816(acc[0][2 * tp + 1], a0, a1, a2, a3, b2, b3);
                mma16816(acc[1][2 * tp], a4, a5, a6, a7, b0, b1);
                mma16816(acc[1][2 * tp + 1], a4, a5, a6, a7, b2, b3);
            }
        }

        // h-tile boundary: fused epilogue, reset accumulators
        if ((g & 3) == 3) {
            const int h0 = (g >> 2) * 128;
#pragma unroll
            for (int tm = 0; tm < 2; tm++) {
#pragma unroll
                for (int rh = 0; rh < 2; rh++) {
                    int m_local = wm * 32 + tm * 16 + rh * 8 + (lane >> 2);
                    float cov = coverage[m0 + m_local];
                    float rs = 0.0f;
#pragma unroll
                    for (int tn = 0; tn < 4; tn++) {
                        int h = h0 + wn * 32 + tn * 8 + (lane & 3) * 2;
                        float p0 = acc[tm][tn][rh * 2 + 0] + s_base[h] +
                                   cov * s_wcov[h];
                        float p1 = acc[tm][tn][rh * 2 + 1] + s_base[h + 1] +
                                   cov * s_wcov[h + 1];
                        rs += fast_tanh(p0) * s_w2[h] +
                              fast_tanh(p1) * s_w2[h + 1];
                    }
                    rs += __shfl_xor_sync(0xffffffffu, rs, 1);
                    rs += __shfl_xor_sync(0xffffffffu, rs, 2);
                    if ((lane & 3) == 0) s_red[m_local * 4 + wn] = rs;
#pragma unroll
                    for (int tn = 0; tn < 4; tn++) {
                        acc[tm][tn][rh * 2 + 0] = 0.0f;
                        acc[tm][tn][rh * 2 + 1] = 0.0f;
                    }
                }
            }
            __syncthreads();
            if (tid < 128)
                s_lac[tid] += (s_red[tid * 4] + s_red[tid * 4 + 1]) +
                              (s_red[tid * 4 + 2] + s_red[tid * 4 + 3]);
        }

        if (g < NST - 1) CP_WAIT0();
        __syncthreads();
    }

    if (tid < 128) g_logits[m0 + tid] = s_lac[tid];
}

// ---------------------------------------------------------------------------
// K3: per-batch masked softmax
// ---------------------------------------------------------------------------
__global__ __launch_bounds__(256) void softmax_kernel(const int* __restrict__ tlen,
                                                      float* __restrict__ att_out) {
    int b = blockIdx.x;
    int tid = threadIdx.x;
    __shared__ float sl[NL];
    __shared__ float rbuf[256];
    int len = tlen[b];

    for (int l = tid; l < len; l += 256) sl[l] = g_logits[b * NL + l];
    __syncthreads();

    float mx = -INFINITY;
    for (int l = tid; l < len; l += 256) mx = fmaxf(mx, sl[l]);
    rbuf[tid] = mx;
    __syncthreads();
    for (int s = 128; s > 0; s >>= 1) {
        if (tid < s) rbuf[tid] = fmaxf(rbuf[tid], rbuf[tid + s]);
        __syncthreads();
    }
    mx = rbuf[0];
    __syncthreads();

    float sum = 0.0f;
    for (int l = tid; l < len; l += 256) {
        float e = fast_exp(sl[l] - mx);
        sl[l] = e;
        sum += e;
    }
    rbuf[tid] = sum;
    __syncthreads();
    for (int s = 128; s > 0; s >>= 1) {
        if (tid < s) rbuf[tid] = rbuf[tid] + rbuf[tid + s];
        __syncthreads();
    }
    float inv = 1.0f / rbuf[0];

    for (int l = tid; l < NL; l += 256)
        att_out[b * NL + l] = (l < len) ? sl[l] * inv : 0.0f;
}

// ---------------------------------------------------------------------------
// K4/K5: context partials + reduce
// ---------------------------------------------------------------------------
__global__ __launch_bounds__(256) void ctx_part_kernel(
    const float* __restrict__ ts, const float* __restrict__ att,
    const int* __restrict__ tlen) {
    int b = blockIdx.x;
    int c = blockIdx.y;
    int tid = threadIdx.x;
    float* out = g_ctx_part + ((size_t)c * NB + b) * 512;

    if (c * 128 >= tlen[b]) {
        out[tid] = 0.0f;
        out[tid + 256] = 0.0f;
        return;
    }

    __shared__ float sa[128];
    if (tid < 128) sa[tid] = att[b * NL + c * 128 + tid];
    __syncthreads();

    const float* base = ts + ((size_t)b * NL + c * 128) * 512;
    float a0 = 0.f, a1 = 0.f;
#pragma unroll 4
    for (int l = 0; l < 128; l++) {
        float wv = sa[l];
        a0 += wv * base[(size_t)l * 512 + tid];
        a1 += wv * base[(size_t)l * 512 + 256 + tid];
    }
    out[tid] = a0;
    out[tid + 256] = a1;
}

__global__ __launch_bounds__(512) void ctx_reduce_kernel(float* __restrict__ ctx) {
    int b = blockIdx.x;
    int f = threadIdx.x;
    float s = 0.0f;
#pragma unroll
    for (int c = 0; c < 32; c++) s += g_ctx_part[((size_t)c * NB + b) * 512 + f];
    ctx[b * 512 + f] = s;
}

// ---------------------------------------------------------------------------
// Launch
// ---------------------------------------------------------------------------
extern "C" void kernel_launch(void* const* d_in, const int* in_sizes, int n_in,
                              void* d_out, int out_size) {
    const float* ts  = (const float*)d_in[0];
    const float* ss  = (const float*)d_in[1];
    const float* cov = (const float*)d_in[2];
    const float* W1  = (const float*)d_in[3];
    const float* b1  = (const float*)d_in[4];
    const float* W2  = (const float*)d_in[5];
    const int*   tl  = (const int*)d_in[7];
    float* out = (float*)d_out;
    float* ctx_out = out;             // [32,512]
    float* att_out = out + NB * 512;  // [32,4096]

    cudaFuncSetAttribute(gemm_kernel,
                         cudaFuncAttributeMaxDynamicSharedMemorySize, SMEM_TOTAL);

    convA_kernel<<<1024, 256>>>(ts, tl);
    convB_kernel<<<NH, 512>>>(W1);
    base_kernel<<<NB, 512>>>(ss, W1, b1);
    gemm_kernel<<<1024, 512, SMEM_TOTAL>>>(W1, W2, cov, tl);
    softmax_kernel<<<NB, 256>>>(tl, att_out);
    ctx_part_kernel<<<dim3(NB, 32), 256>>>(ts, att_out, tl);
    ctx_reduce_kernel<<<NB, 512>>>(ctx_out);
}

// round 8
// speedup vs baseline: 1.9388x; 1.0378x over previous
#include <cuda_runtime.h>
#include <cuda_fp16.h>
#include <math.h>
#include <stdint.h>

// ---------------------------------------------------------------------------
// Problem constants
// ---------------------------------------------------------------------------
#define NB   32
#define NL   4096
#define NH   512
#define NC   1025
#define MTOT (NB * NL)   // 131072

#define MT   128         // m rows per CTA
#define NST  16          // 4 h-tiles x 4 k-stages of 128

// SMEM layout
#define A_ROWB 1040                    // 512 fp16 + 16B pad
#define SM_A   0
#define A_BYTES (128 * A_ROWB)         // 133120
#define B_ROWB 272                     // 128 fp16 + 16B pad
#define B_TILE (128 * B_ROWB)          // 34816
#define SM_B   A_BYTES
#define SM_TAB (A_BYTES + 2 * B_TILE)  // 202752
// tables: w2[512] base[512] wcov[512] red[512] lac[128]
#define SMEM_TOTAL (SM_TAB + 8704)     // 211456

// ---------------------------------------------------------------------------
// Device scratch (static; no runtime allocation)
// ---------------------------------------------------------------------------
__device__ float g_base[NB * NH];
__device__ float g_logits[MTOT];
__device__ __half g_Bf[NH * 512];             // W1[:,0:512] fp16
__device__ float g_ctx_part[32 * NB * 512];

// ---------------------------------------------------------------------------
// helpers
// ---------------------------------------------------------------------------
__device__ __forceinline__ uint32_t smem_u32(const void* p) {
    uint32_t a;
    asm("{ .reg .u64 t; cvta.to.shared.u64 t, %1; cvt.u32.u64 %0, t; }"
        : "=r"(a) : "l"(p));
    return a;
}

__device__ __forceinline__ void ldsm4(uint32_t addr, uint32_t& r0, uint32_t& r1,
                                      uint32_t& r2, uint32_t& r3) {
    asm volatile("ldmatrix.sync.aligned.m8n8.x4.shared.b16 {%0,%1,%2,%3}, [%4];"
                 : "=r"(r0), "=r"(r1), "=r"(r2), "=r"(r3) : "r"(addr));
}

__device__ __forceinline__ void mma16816(float* d, uint32_t a0, uint32_t a1,
                                         uint32_t a2, uint32_t a3, uint32_t b0,
                                         uint32_t b1) {
    asm volatile(
        "mma.sync.aligned.m16n8k16.row.col.f32.f16.f16.f32 "
        "{%0,%1,%2,%3}, {%4,%5,%6,%7}, {%8,%9}, {%0,%1,%2,%3};"
        : "+f"(d[0]), "+f"(d[1]), "+f"(d[2]), "+f"(d[3])
        : "r"(a0), "r"(a1), "r"(a2), "r"(a3), "r"(b0), "r"(b1));
}

__device__ __forceinline__ void cpasync16(uint32_t dst, const void* src) {
    asm volatile("cp.async.cg.shared.global [%0], [%1], 16;"
                 :: "r"(dst), "l"(src) : "memory");
}
#define CP_COMMIT() asm volatile("cp.async.commit_group;" ::: "memory")
#define CP_WAIT0()  asm volatile("cp.async.wait_group 0;" ::: "memory")

__device__ __forceinline__ float fast_tanh(float x) {
    float t = x * 2.885390081777927f;  // 2*log2(e)
    float e;
    asm("ex2.approx.f32 %0, %1;" : "=f"(e) : "f"(t));
    float r;
    asm("rcp.approx.f32 %0, %1;" : "=f"(r) : "f"(e + 1.0f));
    return 1.0f - 2.0f * r;
}
__device__ __forceinline__ float fast_exp(float x) {
    float t = x * 1.4426950408889634f;
    float e;
    asm("ex2.approx.f32 %0, %1;" : "=f"(e) : "f"(t));
    return e;
}
__device__ __forceinline__ uint32_t pack_h2(__half a, __half b) {
    __half2 v = __halves2half2(a, b);
    return *reinterpret_cast<uint32_t*>(&v);
}

// ---------------------------------------------------------------------------
// K-1b: W1[:,0:512] -> fp16
// ---------------------------------------------------------------------------
__global__ void convB_kernel(const float* __restrict__ W1) {
    int h = blockIdx.x;
    int k = threadIdx.x;
    g_Bf[h * 512 + k] = __float2half_rn(W1[(size_t)h * NC + k]);
}

// ---------------------------------------------------------------------------
// K0: base[b,h] = b1[h] + sum_c summary[b,c]*W1[h,512+c]  (exact fp32)
// ---------------------------------------------------------------------------
__global__ void base_kernel(const float* __restrict__ summary,
                            const float* __restrict__ W1,
                            const float* __restrict__ b1) {
    int b = blockIdx.x;
    int h = threadIdx.x;
    __shared__ float ss[512];
    ss[h] = summary[b * 512 + h];
    __syncthreads();
    const float* w = W1 + (size_t)h * NC + 512;
    float acc = b1[h];
#pragma unroll 8
    for (int c = 0; c < 512; c++) acc += ss[c] * w[c];
    g_base[b * NH + h] = acc;
}

// ---------------------------------------------------------------------------
// K1: HMMA GEMM. ts fp32 loaded+converted in prologue into resident SMEM A;
// flat 16-stage B pipeline. 512 threads = 16 warps (4m x 4n).
// ---------------------------------------------------------------------------
__global__ __launch_bounds__(512, 1) void gemm_kernel(
    const float* __restrict__ ts, const float* __restrict__ W1,
    const float* __restrict__ W2, const float* __restrict__ coverage,
    const int* __restrict__ tlen) {
    extern __shared__ char smem[];
    const uint32_t sb = smem_u32(smem);
    const int tid = threadIdx.x;
    const int lane = tid & 31;
    const int warp = tid >> 5;
    const int wm = warp & 3;   // m quadrant (32 rows)
    const int wn = warp >> 2;  // n quadrant (32 cols)

    const int bid = blockIdx.x;
    const int b = bid >> 5;
    const int l0 = (bid & 31) * 128;
    if (l0 >= tlen[b]) return;
    const size_t m0 = (size_t)bid * MT;

    float* s_w2 = (float*)(smem + SM_TAB);            // 512
    float* s_base = (float*)(smem + SM_TAB + 2048);   // 512
    float* s_wcov = (float*)(smem + SM_TAB + 4096);   // 512
    float* s_red = (float*)(smem + SM_TAB + 6144);    // 128 x 4
    float* s_lac = (float*)(smem + SM_TAB + 8192);    // 128

    if (tid < 128) s_lac[tid] = 0.0f;

    // ---- prologue: B stage 0 (async) + A fp32->fp16 conversion + tables ----
    {
        // B stage 0 (ht=0, k0=0): 2048 16B chunks
#pragma unroll
        for (int i = 0; i < 4; i++) {
            int e = tid + i * 512;
            int r = e >> 4, c = e & 15;
            cpasync16(sb + SM_B + (uint32_t)(r * B_ROWB + c * 16),
                      g_Bf + (size_t)r * 512 + c * 8);
        }
        CP_COMMIT();

        // A: 16384 float4 slots; load fp32, convert, store fp16 to SMEM.
        // 4 chunks of 8 float4 per thread to bound live registers.
#pragma unroll
        for (int ch = 0; ch < 4; ch++) {
            float4 v[8];
#pragma unroll
            for (int i = 0; i < 8; i++) {
                int e = tid + (ch * 8 + i) * 512;
                int r = e >> 7, q = e & 127;
                v[i] = *(const float4*)(ts + (m0 + r) * 512 + q * 4);
            }
#pragma unroll
            for (int i = 0; i < 8; i++) {
                int e = tid + (ch * 8 + i) * 512;
                int r = e >> 7, q = e & 127;
                *(uint2*)(smem + r * A_ROWB + q * 8) = make_uint2(
                    pack_h2(__float2half_rn(v[i].x), __float2half_rn(v[i].y)),
                    pack_h2(__float2half_rn(v[i].z), __float2half_rn(v[i].w)));
            }
        }

        // tables (512 entries each)
        s_w2[tid] = W2[tid];
        s_base[tid] = g_base[b * NH + tid];
        s_wcov[tid] = W1[(size_t)tid * NC + 1024];
        CP_WAIT0();
        __syncthreads();
    }

    const uint32_t aBase =
        sb + (uint32_t)((wm * 32 + (lane & 15)) * A_ROWB + (lane >> 4) * 16);
    const uint32_t bBase0 =
        sb + SM_B +
        (uint32_t)((wn * 32 + (lane & 7) + ((lane >> 4) & 1) * 8) * B_ROWB +
                   ((lane >> 3) & 1) * 16);

    float acc[2][4][4];
#pragma unroll
    for (int i = 0; i < 2; i++)
#pragma unroll
        for (int j = 0; j < 4; j++)
#pragma unroll
            for (int c = 0; c < 4; c++) acc[i][j][c] = 0.0f;

    const int cr = tid >> 4;   // B cp.async row base (0..31), +32 per i
    const int ccB = tid & 15;  // 16B chunk in B row

    for (int g = 0; g < NST; g++) {
        const uint32_t bo = (uint32_t)((g & 1) * B_TILE);

        // issue next B stage into the other buffer
        if (g < NST - 1) {
            const int gn = g + 1;
            const int htn = gn >> 2, sn = gn & 3;
            const uint32_t nbo = (uint32_t)((gn & 1) * B_TILE);
#pragma unroll
            for (int i = 0; i < 4; i++) {
                int r = cr + i * 32;
                cpasync16(sb + SM_B + nbo + (uint32_t)(r * B_ROWB + ccB * 16),
                          g_Bf + (size_t)(htn * 128 + r) * 512 + sn * 128 +
                              ccB * 8);
            }
            CP_COMMIT();
        }

        // compute stage g: A columns [(g&3)*128, +128), B buffer bo
        const uint32_t aOff = (uint32_t)((g & 3) * 256);
#pragma unroll
        for (int ks = 0; ks < 8; ks++) {
            uint32_t a0, a1, a2, a3, a4, a5, a6, a7;
            ldsm4(aBase + aOff + ks * 32, a0, a1, a2, a3);
            ldsm4(aBase + aOff + ks * 32 + 16 * A_ROWB, a4, a5, a6, a7);
#pragma unroll
            for (int tp = 0; tp < 2; tp++) {
                uint32_t b0, b1, b2, b3;
                ldsm4(bBase0 + bo + ks * 32 + tp * 16 * B_ROWB, b0, b1, b2, b3);
                mma16816(acc[0][2 * tp], a0, a1, a2, a3, b0, b1);
                mma16816(acc[0][2 * tp + 1], a0, a1, a2, a3, b2, b3);
                mma16816(acc[1][2 * tp], a4, a5, a6, a7, b0, b1);
                mma16816(acc[1][2 * tp + 1], a4, a5, a6, a7, b2, b3);
            }
        }

        // h-tile boundary: fused epilogue, reset accumulators
        if ((g & 3) == 3) {
            const int h0 = (g >> 2) * 128;
#pragma unroll
            for (int tm = 0; tm < 2; tm++) {
#pragma unroll
                for (int rh = 0; rh < 2; rh++) {
                    int m_local = wm * 32 + tm * 16 + rh * 8 + (lane >> 2);
                    float cov = coverage[m0 + m_local];
                    float rs = 0.0f;
#pragma unroll
                    for (int tn = 0; tn < 4; tn++) {
                        int h = h0 + wn * 32 + tn * 8 + (lane & 3) * 2;
                        float p0 = acc[tm][tn][rh * 2 + 0] + s_base[h] +
                                   cov * s_wcov[h];
                        float p1 = acc[tm][tn][rh * 2 + 1] + s_base[h + 1] +
                                   cov * s_wcov[h + 1];
                        rs += fast_tanh(p0) * s_w2[h] +
                              fast_tanh(p1) * s_w2[h + 1];
                    }
                    rs += __shfl_xor_sync(0xffffffffu, rs, 1);
                    rs += __shfl_xor_sync(0xffffffffu, rs, 2);
                    if ((lane & 3) == 0) s_red[m_local * 4 + wn] = rs;
#pragma unroll
                    for (int tn = 0; tn < 4; tn++) {
                        acc[tm][tn][rh * 2 + 0] = 0.0f;
                        acc[tm][tn][rh * 2 + 1] = 0.0f;
                    }
                }
            }
            __syncthreads();
            if (tid < 128)
                s_lac[tid] += (s_red[tid * 4] + s_red[tid * 4 + 1]) +
                              (s_red[tid * 4 + 2] + s_red[tid * 4 + 3]);
        }

        if (g < NST - 1) CP_WAIT0();
        __syncthreads();
    }

    if (tid < 128) g_logits[m0 + tid] = s_lac[tid];
}

// ---------------------------------------------------------------------------
// K3: per-batch masked softmax
// ---------------------------------------------------------------------------
__global__ __launch_bounds__(256) void softmax_kernel(const int* __restrict__ tlen,
                                                      float* __restrict__ att_out) {
    int b = blockIdx.x;
    int tid = threadIdx.x;
    __shared__ float sl[NL];
    __shared__ float rbuf[256];
    int len = tlen[b];

    for (int l = tid; l < len; l += 256) sl[l] = g_logits[b * NL + l];
    __syncthreads();

    float mx = -INFINITY;
    for (int l = tid; l < len; l += 256) mx = fmaxf(mx, sl[l]);
    rbuf[tid] = mx;
    __syncthreads();
    for (int s = 128; s > 0; s >>= 1) {
        if (tid < s) rbuf[tid] = fmaxf(rbuf[tid], rbuf[tid + s]);
        __syncthreads();
    }
    mx = rbuf[0];
    __syncthreads();

    float sum = 0.0f;
    for (int l = tid; l < len; l += 256) {
        float e = fast_exp(sl[l] - mx);
        sl[l] = e;
        sum += e;
    }
    rbuf[tid] = sum;
    __syncthreads();
    for (int s = 128; s > 0; s >>= 1) {
        if (tid < s) rbuf[tid] = rbuf[tid] + rbuf[tid + s];
        __syncthreads();
    }
    float inv = 1.0f / rbuf[0];

    for (int l = tid; l < NL; l += 256)
        att_out[b * NL + l] = (l < len) ? sl[l] * inv : 0.0f;
}

// ---------------------------------------------------------------------------
// K4/K5: context partials + reduce
// ---------------------------------------------------------------------------
__global__ __launch_bounds__(256) void ctx_part_kernel(
    const float* __restrict__ ts, const float* __restrict__ att,
    const int* __restrict__ tlen) {
    int b = blockIdx.x;
    int c = blockIdx.y;
    int tid = threadIdx.x;
    float* out = g_ctx_part + ((size_t)c * NB + b) * 512;

    if (c * 128 >= tlen[b]) {
        out[tid] = 0.0f;
        out[tid + 256] = 0.0f;
        return;
    }

    __shared__ float sa[128];
    if (tid < 128) sa[tid] = att[b * NL + c * 128 + tid];
    __syncthreads();

    const float* base = ts + ((size_t)b * NL + c * 128) * 512;
    float a0 = 0.f, a1 = 0.f;
#pragma unroll 4
    for (int l = 0; l < 128; l++) {
        float wv = sa[l];
        a0 += wv * base[(size_t)l * 512 + tid];
        a1 += wv * base[(size_t)l * 512 + 256 + tid];
    }
    out[tid] = a0;
    out[tid + 256] = a1;
}

__global__ __launch_bounds__(512) void ctx_reduce_kernel(float* __restrict__ ctx) {
    int b = blockIdx.x;
    int f = threadIdx.x;
    float s = 0.0f;
#pragma unroll
    for (int c = 0; c < 32; c++) s += g_ctx_part[((size_t)c * NB + b) * 512 + f];
    ctx[b * 512 + f] = s;
}

// ---------------------------------------------------------------------------
// Launch
// ---------------------------------------------------------------------------
extern "C" void kernel_launch(void* const* d_in, const int* in_sizes, int n_in,
                              void* d_out, int out_size) {
    const float* ts  = (const float*)d_in[0];
    const float* ss  = (const float*)d_in[1];
    const float* cov = (const float*)d_in[2];
    const float* W1  = (const float*)d_in[3];
    const float* b1  = (const float*)d_in[4];
    const float* W2  = (const float*)d_in[5];
    const int*   tl  = (const int*)d_in[7];
    float* out = (float*)d_out;
    float* ctx_out = out;             // [32,512]
    float* att_out = out + NB * 512;  // [32,4096]

    cudaFuncSetAttribute(gemm_kernel,
                         cudaFuncAttributeMaxDynamicSharedMemorySize, SMEM_TOTAL);

    convB_kernel<<<NH, 512>>>(W1);
    base_kernel<<<NB, 512>>>(ss, W1, b1);
    gemm_kernel<<<1024, 512, SMEM_TOTAL>>>(ts, W1, W2, cov, tl);
    softmax_kernel<<<NB, 256>>>(tl, att_out);
    ctx_part_kernel<<<dim3(NB, 32), 256>>>(ts, att_out, tl);
    ctx_reduce_kernel<<<NB, 512>>>(ctx_out);
}

// round 9
// speedup vs baseline: 2.0381x; 1.0512x over previous
#include <cuda_runtime.h>
#include <cuda_fp16.h>
#include <math.h>
#include <stdint.h>

// ---------------------------------------------------------------------------
// Problem constants
// ---------------------------------------------------------------------------
#define NB   32
#define NL   4096
#define NH   512
#define NC   1025
#define MTOT (NB * NL)   // 131072

#define MT   128         // m rows per CTA
#define NST  16          // 4 h-tiles x 4 k-stages of 128

// SMEM layout
#define A_ROWB 1040                    // 512 fp16 + 16B pad
#define SM_A   0
#define A_BYTES (128 * A_ROWB)         // 133120
#define B_ROWB 272                     // 128 fp16 + 16B pad
#define B_TILE (128 * B_ROWB)          // 34816
#define SM_B   A_BYTES
#define SM_TAB (A_BYTES + 2 * B_TILE)  // 202752
// tables: w2[512] base[512] wcov[512] red[512] lac[128]
#define SMEM_TOTAL (SM_TAB + 8704)     // 211456

// ---------------------------------------------------------------------------
// Device scratch (static; no runtime allocation)
// ---------------------------------------------------------------------------
__device__ float g_base[NB * NH];
__device__ float g_logits[MTOT];
__device__ __half g_Bf[NH * 512];             // W1[:,0:512] fp16
__device__ float g_ctx_part[32 * NB * 512];

// ---------------------------------------------------------------------------
// helpers
// ---------------------------------------------------------------------------
__device__ __forceinline__ uint32_t smem_u32(const void* p) {
    uint32_t a;
    asm("{ .reg .u64 t; cvta.to.shared.u64 t, %1; cvt.u32.u64 %0, t; }"
        : "=r"(a) : "l"(p));
    return a;
}

__device__ __forceinline__ void ldsm4(uint32_t addr, uint32_t& r0, uint32_t& r1,
                                      uint32_t& r2, uint32_t& r3) {
    asm volatile("ldmatrix.sync.aligned.m8n8.x4.shared.b16 {%0,%1,%2,%3}, [%4];"
                 : "=r"(r0), "=r"(r1), "=r"(r2), "=r"(r3) : "r"(addr));
}

__device__ __forceinline__ void mma16816(float* d, uint32_t a0, uint32_t a1,
                                         uint32_t a2, uint32_t a3, uint32_t b0,
                                         uint32_t b1) {
    asm volatile(
        "mma.sync.aligned.m16n8k16.row.col.f32.f16.f16.f32 "
        "{%0,%1,%2,%3}, {%4,%5,%6,%7}, {%8,%9}, {%0,%1,%2,%3};"
        : "+f"(d[0]), "+f"(d[1]), "+f"(d[2]), "+f"(d[3])
        : "r"(a0), "r"(a1), "r"(a2), "r"(a3), "r"(b0), "r"(b1));
}

__device__ __forceinline__ void cpasync16(uint32_t dst, const void* src) {
    asm volatile("cp.async.cg.shared.global [%0], [%1], 16;"
                 :: "r"(dst), "l"(src) : "memory");
}
#define CP_COMMIT() asm volatile("cp.async.commit_group;" ::: "memory")
#define CP_WAIT0()  asm volatile("cp.async.wait_group 0;" ::: "memory")

__device__ __forceinline__ float fast_tanh(float x) {
    float t = x * 2.885390081777927f;  // 2*log2(e)
    float e;
    asm("ex2.approx.f32 %0, %1;" : "=f"(e) : "f"(t));
    float r;
    asm("rcp.approx.f32 %0, %1;" : "=f"(r) : "f"(e + 1.0f));
    return 1.0f - 2.0f * r;
}
__device__ __forceinline__ float fast_exp(float x) {
    float t = x * 1.4426950408889634f;
    float e;
    asm("ex2.approx.f32 %0, %1;" : "=f"(e) : "f"(t));
    return e;
}
__device__ __forceinline__ uint32_t pack_h2(__half a, __half b) {
    __half2 v = __halves2half2(a, b);
    return *reinterpret_cast<uint32_t*>(&v);
}

// ---------------------------------------------------------------------------
// K-1b: W1[:,0:512] -> fp16
// ---------------------------------------------------------------------------
__global__ void convB_kernel(const float* __restrict__ W1) {
    int h = blockIdx.x;
    int k = threadIdx.x;
    g_Bf[h * 512 + k] = __float2half_rn(W1[(size_t)h * NC + k]);
}

// ---------------------------------------------------------------------------
// K0: base[b,h] = b1[h] + sum_c summary[b,c]*W1[h,512+c]  (exact fp32)
// ---------------------------------------------------------------------------
__global__ void base_kernel(const float* __restrict__ summary,
                            const float* __restrict__ W1,
                            const float* __restrict__ b1) {
    int b = blockIdx.x;
    int h = threadIdx.x;
    __shared__ float ss[512];
    ss[h] = summary[b * 512 + h];
    __syncthreads();
    const float* w = W1 + (size_t)h * NC + 512;
    float acc = b1[h];
#pragma unroll 8
    for (int c = 0; c < 512; c++) acc += ss[c] * w[c];
    g_base[b * NH + h] = acc;
}

// ---------------------------------------------------------------------------
// K1: HMMA GEMM. A fp32->fp16 conversion pipelined through the first h-tile
// (chunk 0 in prologue; chunks 1..3 prefetched+converted under MMA compute).
// Flat 16-stage B pipeline. 512 threads = 16 warps (4m x 4n).
// ---------------------------------------------------------------------------
__global__ __launch_bounds__(512, 1) void gemm_kernel(
    const float* __restrict__ ts, const float* __restrict__ W1,
    const float* __restrict__ W2, const float* __restrict__ coverage,
    const int* __restrict__ tlen) {
    extern __shared__ char smem[];
    const uint32_t sb = smem_u32(smem);
    const int tid = threadIdx.x;
    const int lane = tid & 31;
    const int warp = tid >> 5;
    const int wm = warp & 3;   // m quadrant (32 rows)
    const int wn = warp >> 2;  // n quadrant (32 cols)

    const int bid = blockIdx.x;
    const int b = bid >> 5;
    const int l0 = (bid & 31) * 128;
    if (l0 >= tlen[b]) return;
    const size_t m0 = (size_t)bid * MT;

    float* s_w2 = (float*)(smem + SM_TAB);            // 512
    float* s_base = (float*)(smem + SM_TAB + 2048);   // 512
    float* s_wcov = (float*)(smem + SM_TAB + 4096);   // 512
    float* s_red = (float*)(smem + SM_TAB + 6144);    // 128 x 4
    float* s_lac = (float*)(smem + SM_TAB + 8192);    // 128

    if (tid < 128) s_lac[tid] = 0.0f;

    // A-chunk prefetch coordinates: chunk = 128 rows x 128 cols fp32
    // = 4096 float4 slots; 8 per thread (two groups of 4).
    const int ar = tid >> 2;         // base row pair: e>>5 with e=tid+i*512
    (void)ar;

    // ---- prologue: B stage 0 (async) + A chunk 0 conversion + tables ----
    {
        // B stage 0 (ht=0, k0=0): 2048 16B chunks
#pragma unroll
        for (int i = 0; i < 4; i++) {
            int e = tid + i * 512;
            int r = e >> 4, c = e & 15;
            cpasync16(sb + SM_B + (uint32_t)(r * B_ROWB + c * 16),
                      g_Bf + (size_t)r * 512 + c * 8);
        }
        CP_COMMIT();

        // A chunk 0: 4096 float4 slots (cols 0..127)
#pragma unroll
        for (int i = 0; i < 8; i++) {
            int e = tid + i * 512;
            int r = e >> 5, q = e & 31;
            float4 v = *(const float4*)(ts + (m0 + r) * 512 + q * 4);
            *(uint2*)(smem + r * A_ROWB + q * 8) = make_uint2(
                pack_h2(__float2half_rn(v.x), __float2half_rn(v.y)),
                pack_h2(__float2half_rn(v.z), __float2half_rn(v.w)));
        }

        // tables (512 entries each)
        s_w2[tid] = W2[tid];
        s_base[tid] = g_base[b * NH + tid];
        s_wcov[tid] = W1[(size_t)tid * NC + 1024];
        CP_WAIT0();
        __syncthreads();
    }

    const uint32_t aBase =
        sb + (uint32_t)((wm * 32 + (lane & 15)) * A_ROWB + (lane >> 4) * 16);
    const uint32_t bBase0 =
        sb + SM_B +
        (uint32_t)((wn * 32 + (lane & 7) + ((lane >> 4) & 1) * 8) * B_ROWB +
                   ((lane >> 3) & 1) * 16);

    float acc[2][4][4];
#pragma unroll
    for (int i = 0; i < 2; i++)
#pragma unroll
        for (int j = 0; j < 4; j++)
#pragma unroll
            for (int c = 0; c < 4; c++) acc[i][j][c] = 0.0f;

    const int cr = tid >> 4;   // B cp.async row base (0..31), +32 per i
    const int ccB = tid & 15;  // 16B chunk in B row

    for (int g = 0; g < NST; g++) {
        const uint32_t bo = (uint32_t)((g & 1) * B_TILE);

        // issue next B stage into the other buffer
        if (g < NST - 1) {
            const int gn = g + 1;
            const int htn = gn >> 2, sn = gn & 3;
            const uint32_t nbo = (uint32_t)((gn & 1) * B_TILE);
#pragma unroll
            for (int i = 0; i < 4; i++) {
                int r = cr + i * 32;
                cpasync16(sb + SM_B + nbo + (uint32_t)(r * B_ROWB + ccB * 16),
                          g_Bf + (size_t)(htn * 128 + r) * 512 + sn * 128 +
                              ccB * 8);
            }
            CP_COMMIT();
        }

        // A prefetch (first h-tile only): chunk g+1, group 0 (slots 0..2047)
        const bool aPre = (g < 3);
        float4 av[4];
        if (aPre) {
#pragma unroll
            for (int i = 0; i < 4; i++) {
                int e = tid + i * 512;
                int r = e >> 5, q = e & 31;
                av[i] = *(const float4*)(ts + (m0 + r) * 512 + (g + 1) * 128 +
                                         q * 4);
            }
        }

        // compute stage g, first half (ks 0..3)
        const uint32_t aOff = (uint32_t)((g & 3) * 256);
#pragma unroll
        for (int ks = 0; ks < 4; ks++) {
            uint32_t a0, a1, a2, a3, a4, a5, a6, a7;
            ldsm4(aBase + aOff + ks * 32, a0, a1, a2, a3);
            ldsm4(aBase + aOff + ks * 32 + 16 * A_ROWB, a4, a5, a6, a7);
#pragma unroll
            for (int tp = 0; tp < 2; tp++) {
                uint32_t b0, b1, b2, b3;
                ldsm4(bBase0 + bo + ks * 32 + tp * 16 * B_ROWB, b0, b1, b2, b3);
                mma16816(acc[0][2 * tp], a0, a1, a2, a3, b0, b1);
                mma16816(acc[0][2 * tp + 1], a0, a1, a2, a3, b2, b3);
                mma16816(acc[1][2 * tp], a4, a5, a6, a7, b0, b1);
                mma16816(acc[1][2 * tp + 1], a4, a5, a6, a7, b2, b3);
            }
        }

        // convert+store group 0; prefetch group 1 (slots 2048..4095)
        if (aPre) {
#pragma unroll
            for (int i = 0; i < 4; i++) {
                int e = tid + i * 512;
                int r = e >> 5, q = e & 31;
                *(uint2*)(smem + r * A_ROWB + (g + 1) * 256 + q * 8) =
                    make_uint2(pack_h2(__float2half_rn(av[i].x),
                                       __float2half_rn(av[i].y)),
                               pack_h2(__float2half_rn(av[i].z),
                                       __float2half_rn(av[i].w)));
            }
#pragma unroll
            for (int i = 0; i < 4; i++) {
                int e = tid + (i + 4) * 512;
                int r = e >> 5, q = e & 31;
                av[i] = *(const float4*)(ts + (m0 + r) * 512 + (g + 1) * 128 +
                                         q * 4);
            }
        }

        // compute stage g, second half (ks 4..7)
#pragma unroll
        for (int ks = 4; ks < 8; ks++) {
            uint32_t a0, a1, a2, a3, a4, a5, a6, a7;
            ldsm4(aBase + aOff + ks * 32, a0, a1, a2, a3);
            ldsm4(aBase + aOff + ks * 32 + 16 * A_ROWB, a4, a5, a6, a7);
#pragma unroll
            for (int tp = 0; tp < 2; tp++) {
                uint32_t b0, b1, b2, b3;
                ldsm4(bBase0 + bo + ks * 32 + tp * 16 * B_ROWB, b0, b1, b2, b3);
                mma16816(acc[0][2 * tp], a0, a1, a2, a3, b0, b1);
                mma16816(acc[0][2 * tp + 1], a0, a1, a2, a3, b2, b3);
                mma16816(acc[1][2 * tp], a4, a5, a6, a7, b0, b1);
                mma16816(acc[1][2 * tp + 1], a4, a5, a6, a7, b2, b3);
            }
        }

        // convert+store group 1
        if (aPre) {
#pragma unroll
            for (int i = 0; i < 4; i++) {
                int e = tid + (i + 4) * 512;
                int r = e >> 5, q = e & 31;
                *(uint2*)(smem + r * A_ROWB + (g + 1) * 256 + q * 8) =
                    make_uint2(pack_h2(__float2half_rn(av[i].x),
                                       __float2half_rn(av[i].y)),
                               pack_h2(__float2half_rn(av[i].z),
                                       __float2half_rn(av[i].w)));
            }
        }

        // h-tile boundary: fused epilogue, reset accumulators
        if ((g & 3) == 3) {
            const int h0 = (g >> 2) * 128;
#pragma unroll
            for (int tm = 0; tm < 2; tm++) {
#pragma unroll
                for (int rh = 0; rh < 2; rh++) {
                    int m_local = wm * 32 + tm * 16 + rh * 8 + (lane >> 2);
                    float cov = coverage[m0 + m_local];
                    float rs = 0.0f;
#pragma unroll
                    for (int tn = 0; tn < 4; tn++) {
                        int h = h0 + wn * 32 + tn * 8 + (lane & 3) * 2;
                        float p0 = acc[tm][tn][rh * 2 + 0] + s_base[h] +
                                   cov * s_wcov[h];
                        float p1 = acc[tm][tn][rh * 2 + 1] + s_base[h + 1] +
                                   cov * s_wcov[h + 1];
                        rs += fast_tanh(p0) * s_w2[h] +
                              fast_tanh(p1) * s_w2[h + 1];
                    }
                    rs += __shfl_xor_sync(0xffffffffu, rs, 1);
                    rs += __shfl_xor_sync(0xffffffffu, rs, 2);
                    if ((lane & 3) == 0) s_red[m_local * 4 + wn] = rs;
#pragma unroll
                    for (int tn = 0; tn < 4; tn++) {
                        acc[tm][tn][rh * 2 + 0] = 0.0f;
                        acc[tm][tn][rh * 2 + 1] = 0.0f;
                    }
                }
            }
            __syncthreads();
            if (tid < 128)
                s_lac[tid] += (s_red[tid * 4] + s_red[tid * 4 + 1]) +
                              (s_red[tid * 4 + 2] + s_red[tid * 4 + 3]);
        }

        if (g < NST - 1) CP_WAIT0();
        __syncthreads();
    }

    if (tid < 128) g_logits[m0 + tid] = s_lac[tid];
}

// ---------------------------------------------------------------------------
// K3: per-batch masked softmax
// ---------------------------------------------------------------------------
__global__ __launch_bounds__(256) void softmax_kernel(const int* __restrict__ tlen,
                                                      float* __restrict__ att_out) {
    int b = blockIdx.x;
    int tid = threadIdx.x;
    __shared__ float sl[NL];
    __shared__ float rbuf[256];
    int len = tlen[b];

    for (int l = tid; l < len; l += 256) sl[l] = g_logits[b * NL + l];
    __syncthreads();

    float mx = -INFINITY;
    for (int l = tid; l < len; l += 256) mx = fmaxf(mx, sl[l]);
    rbuf[tid] = mx;
    __syncthreads();
    for (int s = 128; s > 0; s >>= 1) {
        if (tid < s) rbuf[tid] = fmaxf(rbuf[tid], rbuf[tid + s]);
        __syncthreads();
    }
    mx = rbuf[0];
    __syncthreads();

    float sum = 0.0f;
    for (int l = tid; l < len; l += 256) {
        float e = fast_exp(sl[l] - mx);
        sl[l] = e;
        sum += e;
    }
    rbuf[tid] = sum;
    __syncthreads();
    for (int s = 128; s > 0; s >>= 1) {
        if (tid < s) rbuf[tid] = rbuf[tid] + rbuf[tid + s];
        __syncthreads();
    }
    float inv = 1.0f / rbuf[0];

    for (int l = tid; l < NL; l += 256)
        att_out[b * NL + l] = (l < len) ? sl[l] * inv : 0.0f;
}

// ---------------------------------------------------------------------------
// K4/K5: context partials + reduce
// ---------------------------------------------------------------------------
__global__ __launch_bounds__(256) void ctx_part_kernel(
    const float* __restrict__ ts, const float* __restrict__ att,
    const int* __restrict__ tlen) {
    int b = blockIdx.x;
    int c = blockIdx.y;
    int tid = threadIdx.x;
    float* out = g_ctx_part + ((size_t)c * NB + b) * 512;

    if (c * 128 >= tlen[b]) {
        out[tid] = 0.0f;
        out[tid + 256] = 0.0f;
        return;
    }

    __shared__ float sa[128];
    if (tid < 128) sa[tid] = att[b * NL + c * 128 + tid];
    __syncthreads();

    const float* base = ts + ((size_t)b * NL + c * 128) * 512;
    float a0 = 0.f, a1 = 0.f;
#pragma unroll 4
    for (int l = 0; l < 128; l++) {
        float wv = sa[l];
        a0 += wv * base[(size_t)l * 512 + tid];
        a1 += wv * base[(size_t)l * 512 + 256 + tid];
    }
    out[tid] = a0;
    out[tid + 256] = a1;
}

__global__ __launch_bounds__(512) void ctx_reduce_kernel(float* __restrict__ ctx) {
    int b = blockIdx.x;
    int f = threadIdx.x;
    float s = 0.0f;
#pragma unroll
    for (int c = 0; c < 32; c++) s += g_ctx_part[((size_t)c * NB + b) * 512 + f];
    ctx[b * 512 + f] = s;
}

// ---------------------------------------------------------------------------
// Launch
// ---------------------------------------------------------------------------
extern "C" void kernel_launch(void* const* d_in, const int* in_sizes, int n_in,
                              void* d_out, int out_size) {
    const float* ts  = (const float*)d_in[0];
    const float* ss  = (const float*)d_in[1];
    const float* cov = (const float*)d_in[2];
    const float* W1  = (const float*)d_in[3];
    const float* b1  = (const float*)d_in[4];
    const float* W2  = (const float*)d_in[5];
    const int*   tl  = (const int*)d_in[7];
    float* out = (float*)d_out;
    float* ctx_out = out;             // [32,512]
    float* att_out = out + NB * 512;  // [32,4096]

    cudaFuncSetAttribute(gemm_kernel,
                         cudaFuncAttributeMaxDynamicSharedMemorySize, SMEM_TOTAL);

    convB_kernel<<<NH, 512>>>(W1);
    base_kernel<<<NB, 512>>>(ss, W1, b1);
    gemm_kernel<<<1024, 512, SMEM_TOTAL>>>(ts, W1, W2, cov, tl);
    softmax_kernel<<<NB, 256>>>(tl, att_out);
    ctx_part_kernel<<<dim3(NB, 32), 256>>>(ts, att_out, tl);
    ctx_reduce_kernel<<<NB, 512>>>(ctx_out);
}